// round 5
// baseline (speedup 1.0000x reference)
#include <cuda_runtime.h>
#include <cstdint>

// IWT (inverse 2x2 Haar): x (B=16, 4C=256, H=128, W=128) fp32 -> out (B, C=64, 2H, 2W)
//
// h00 = .5(a-b-c+d) -> out[2h,2w]    h01 = .5(a+b-c-d) -> out[2h,2w+1]
// h10 = .5(a-b+c-d) -> out[2h+1,2w]  h11 = .5(a+b+c+d) -> out[2h+1,2w+1]
//
// R5: single-wave persistent geometry. 1024 blocks x 256 threads, each thread
// owns one (ch, h, w4) site and loops over all B=16 batches. Batch stride is
// the SAME constant (4,194,304 floats) for input and output, so the loop body
// is pure pointer-increment + 4x LDG.128 + 2x STG.256. Eliminates ~17 wave
// transitions of the R4 16384-block launch.

#define B_  16
#define C_  64
#define H_  128
#define W_  128
#define SUBBAND_STRIDE_ (C_ * H_ * W_)  // 1,048,576 floats between subband groups
#define OW_ (2 * W_)                    // 256
#define WQ_ (W_ / 4)                    // 32
#define BATCH_STRIDE_ (4 * C_ * H_ * W_) // 4,194,304 floats (= in & out batch stride)

__device__ __forceinline__ void stg256(float* p,
                                       float v0, float v1, float v2, float v3,
                                       float v4, float v5, float v6, float v7) {
    asm volatile(
        "st.global.v8.f32 [%0], {%1, %2, %3, %4, %5, %6, %7, %8};"
        :: "l"(p), "f"(v0), "f"(v1), "f"(v2), "f"(v3),
           "f"(v4), "f"(v5), "f"(v6), "f"(v7)
        : "memory");
}

__global__ __launch_bounds__(256)
void iwt_kernel(const float* __restrict__ x, float* __restrict__ out) {
    // tid covers (ch, h, w4): 64*128*32 = 262,144 threads
    int tid = blockIdx.x * blockDim.x + threadIdx.x;

    int w4   = tid & (WQ_ - 1);          // 0..31
    int rest = tid >> 5;
    int h    = rest & (H_ - 1);          // 0..127
    int ch   = rest >> 7;                // 0..63

    // b = 0 base addresses
    const float* in_p  = x + ((ch * H_ + h) * W_ + (w4 << 2));
    float*       out_p = out + ((ch * (2 * H_) + (h << 1)) * OW_ + (w4 << 3));

#pragma unroll 1
    for (int b = 0; b < B_; b++) {
        const float4 va = *reinterpret_cast<const float4*>(in_p);
        const float4 vb = *reinterpret_cast<const float4*>(in_p + 1 * SUBBAND_STRIDE_);
        const float4 vc = *reinterpret_cast<const float4*>(in_p + 2 * SUBBAND_STRIDE_);
        const float4 vd = *reinterpret_cast<const float4*>(in_p + 3 * SUBBAND_STRIDE_);

        const float a0 = va.x, a1 = va.y, a2 = va.z, a3 = va.w;
        const float b0 = vb.x, b1 = vb.y, b2 = vb.z, b3 = vb.w;
        const float c0 = vc.x, c1 = vc.y, c2 = vc.z, c3 = vc.w;
        const float d0 = vd.x, d1 = vd.y, d2 = vd.z, d3 = vd.w;

        float h00_0 = 0.5f * (a0 - b0 - c0 + d0);
        float h01_0 = 0.5f * (a0 + b0 - c0 - d0);
        float h10_0 = 0.5f * (a0 - b0 + c0 - d0);
        float h11_0 = 0.5f * (a0 + b0 + c0 + d0);

        float h00_1 = 0.5f * (a1 - b1 - c1 + d1);
        float h01_1 = 0.5f * (a1 + b1 - c1 - d1);
        float h10_1 = 0.5f * (a1 - b1 + c1 - d1);
        float h11_1 = 0.5f * (a1 + b1 + c1 + d1);

        float h00_2 = 0.5f * (a2 - b2 - c2 + d2);
        float h01_2 = 0.5f * (a2 + b2 - c2 - d2);
        float h10_2 = 0.5f * (a2 - b2 + c2 - d2);
        float h11_2 = 0.5f * (a2 + b2 + c2 + d2);

        float h00_3 = 0.5f * (a3 - b3 - c3 + d3);
        float h01_3 = 0.5f * (a3 + b3 - c3 - d3);
        float h10_3 = 0.5f * (a3 - b3 + c3 - d3);
        float h11_3 = 0.5f * (a3 + b3 + c3 + d3);

        stg256(out_p,
               h00_0, h01_0, h00_1, h01_1, h00_2, h01_2, h00_3, h01_3);
        stg256(out_p + OW_,
               h10_0, h11_0, h10_1, h11_1, h10_2, h11_2, h10_3, h11_3);

        in_p  += BATCH_STRIDE_;
        out_p += BATCH_STRIDE_;
    }
}

extern "C" void kernel_launch(void* const* d_in, const int* in_sizes, int n_in,
                              void* d_out, int out_size) {
    const float* x = (const float*)d_in[0];
    float* out = (float*)d_out;

    const int total_threads = C_ * H_ * WQ_;  // 262,144
    const int block = 256;
    const int grid = total_threads / block;   // 1024 blocks -> single wave

    iwt_kernel<<<grid, block>>>(x, out);
}

// round 6
// speedup vs baseline: 1.1503x; 1.1503x over previous
#include <cuda_runtime.h>
#include <cstdint>

// IWT (inverse 2x2 Haar): x (B=16, 4C=256, H=128, W=128) fp32 -> out (B, C=64, 2H, 2W)
//
// h00 = .5(a-b-c+d) -> out[2h,2w]    h01 = .5(a+b-c-d) -> out[2h,2w+1]
// h10 = .5(a-b+c-d) -> out[2h+1,2w]  h11 = .5(a+b+c+d) -> out[2h+1,2w+1]
//
// R6: R4 body (one-shot 4x LDG.128 + 2x STG.256 per thread, 32 regs) with
// 512-thread blocks: each block covers 16 h-rows of one (b,ch) plane ->
// longer contiguous DRAM runs per resident block (4x8KB read, 32KB write).
// R5's persistent-loop geometry regressed (serialized per-thread MLP); the
// many-block one-shot structure is the right one.

#define B_  16
#define C_  64
#define H_  128
#define W_  128
#define SUBBAND_STRIDE_ (C_ * H_ * W_)  // 1,048,576 floats between subband groups
#define OW_ (2 * W_)                    // 256
#define WQ_ (W_ / 4)                    // 32

__device__ __forceinline__ void stg256(float* p,
                                       float v0, float v1, float v2, float v3,
                                       float v4, float v5, float v6, float v7) {
    asm volatile(
        "st.global.v8.f32 [%0], {%1, %2, %3, %4, %5, %6, %7, %8};"
        :: "l"(p), "f"(v0), "f"(v1), "f"(v2), "f"(v3),
           "f"(v4), "f"(v5), "f"(v6), "f"(v7)
        : "memory");
}

__global__ __launch_bounds__(512)
void iwt_kernel(const float* __restrict__ x, float* __restrict__ out) {
    int tid = blockIdx.x * blockDim.x + threadIdx.x;

    int w4   = tid & (WQ_ - 1);          // 0..31
    int rest = tid >> 5;
    int h    = rest & (H_ - 1);          // 0..127
    rest >>= 7;
    int ch   = rest & (C_ - 1);          // 0..63
    int b    = rest >> 6;                // 0..15

    int in_idx = ((b * 256 + ch) * H_ + h) * W_ + (w4 << 2);

    const float4 va = *reinterpret_cast<const float4*>(x + in_idx);
    const float4 vb = *reinterpret_cast<const float4*>(x + in_idx + 1 * SUBBAND_STRIDE_);
    const float4 vc = *reinterpret_cast<const float4*>(x + in_idx + 2 * SUBBAND_STRIDE_);
    const float4 vd = *reinterpret_cast<const float4*>(x + in_idx + 3 * SUBBAND_STRIDE_);

    const float a0 = va.x, a1 = va.y, a2 = va.z, a3 = va.w;
    const float b0 = vb.x, b1 = vb.y, b2 = vb.z, b3 = vb.w;
    const float c0 = vc.x, c1 = vc.y, c2 = vc.z, c3 = vc.w;
    const float d0 = vd.x, d1 = vd.y, d2 = vd.z, d3 = vd.w;

    float h00_0 = 0.5f * (a0 - b0 - c0 + d0);
    float h01_0 = 0.5f * (a0 + b0 - c0 - d0);
    float h10_0 = 0.5f * (a0 - b0 + c0 - d0);
    float h11_0 = 0.5f * (a0 + b0 + c0 + d0);

    float h00_1 = 0.5f * (a1 - b1 - c1 + d1);
    float h01_1 = 0.5f * (a1 + b1 - c1 - d1);
    float h10_1 = 0.5f * (a1 - b1 + c1 - d1);
    float h11_1 = 0.5f * (a1 + b1 + c1 + d1);

    float h00_2 = 0.5f * (a2 - b2 - c2 + d2);
    float h01_2 = 0.5f * (a2 + b2 - c2 - d2);
    float h10_2 = 0.5f * (a2 - b2 + c2 - d2);
    float h11_2 = 0.5f * (a2 + b2 + c2 + d2);

    float h00_3 = 0.5f * (a3 - b3 - c3 + d3);
    float h01_3 = 0.5f * (a3 + b3 - c3 - d3);
    float h10_3 = 0.5f * (a3 - b3 + c3 - d3);
    float h11_3 = 0.5f * (a3 + b3 + c3 + d3);

    int out_row0 = ((b * C_ + ch) * (2 * H_) + (h << 1)) * OW_ + (w4 << 3);
    int out_row1 = out_row0 + OW_;

    stg256(out + out_row0,
           h00_0, h01_0, h00_1, h01_1, h00_2, h01_2, h00_3, h01_3);
    stg256(out + out_row1,
           h10_0, h11_0, h10_1, h11_1, h10_2, h11_2, h10_3, h11_3);
}

extern "C" void kernel_launch(void* const* d_in, const int* in_sizes, int n_in,
                              void* d_out, int out_size) {
    const float* x = (const float*)d_in[0];
    float* out = (float*)d_out;

    const int total_threads = B_ * C_ * H_ * WQ_;  // 4,194,304
    const int block = 512;
    const int grid = total_threads / block;        // 8192

    iwt_kernel<<<grid, block>>>(x, out);
}

// round 7
// speedup vs baseline: 1.1561x; 1.0051x over previous
#include <cuda_runtime.h>
#include <cstdint>

// IWT (inverse 2x2 Haar): x (B=16, 4C=256, H=128, W=128) fp32 -> out (B, C=64, 2H, 2W)
//
// h00 = .5(a-b-c+d) -> out[2h,2w]    h01 = .5(a+b-c-d) -> out[2h,2w+1]
// h10 = .5(a-b+c-d) -> out[2h+1,2w]  h11 = .5(a+b+c+d) -> out[2h+1,2w+1]
//
// R7 (final): R4 geometry — one-shot 4x LDG.128 + 2x STG.256 per thread,
// 32 regs, 16384 x 256 launch — with the butterfly factorized:
//   s0=a+d, s1=a-d, s2=b+c, s3=b-c; t=0.5*s;
//   h00=t0-t2, h01=t1+t3, h10=t1-t3, h11=t0+t2
// (12 FP ops/lane vs 16, shorter load->store dependency chain).
//
// Measured across R1-R6: kernel is HBM-bound at ~6.5 TB/s (82% DRAM) on a
// 1:1 read:write touch-once mix. Cache hints (.cs): neutral. Persistent
// single-wave loop: regression (serialized per-thread MLP). Block 512:
// neutral. 8-wide threads: regression (44 regs -> occ 48%). STG.256 fusion:
// the one real win (-10%). This is the ceiling.

#define B_  16
#define C_  64
#define H_  128
#define W_  128
#define SUBBAND_STRIDE_ (C_ * H_ * W_)  // 1,048,576 floats between subband groups
#define OW_ (2 * W_)                    // 256
#define WQ_ (W_ / 4)                    // 32

__device__ __forceinline__ void stg256(float* p,
                                       float v0, float v1, float v2, float v3,
                                       float v4, float v5, float v6, float v7) {
    asm volatile(
        "st.global.v8.f32 [%0], {%1, %2, %3, %4, %5, %6, %7, %8};"
        :: "l"(p), "f"(v0), "f"(v1), "f"(v2), "f"(v3),
           "f"(v4), "f"(v5), "f"(v6), "f"(v7)
        : "memory");
}

__global__ __launch_bounds__(256)
void iwt_kernel(const float* __restrict__ x, float* __restrict__ out) {
    int tid = blockIdx.x * blockDim.x + threadIdx.x;

    int w4   = tid & (WQ_ - 1);          // 0..31
    int rest = tid >> 5;
    int h    = rest & (H_ - 1);          // 0..127
    rest >>= 7;
    int ch   = rest & (C_ - 1);          // 0..63
    int b    = rest >> 6;                // 0..15

    int in_idx = ((b * 256 + ch) * H_ + h) * W_ + (w4 << 2);

    const float4 va = *reinterpret_cast<const float4*>(x + in_idx);
    const float4 vb = *reinterpret_cast<const float4*>(x + in_idx + 1 * SUBBAND_STRIDE_);
    const float4 vc = *reinterpret_cast<const float4*>(x + in_idx + 2 * SUBBAND_STRIDE_);
    const float4 vd = *reinterpret_cast<const float4*>(x + in_idx + 3 * SUBBAND_STRIDE_);

    float h00[4], h01[4], h10[4], h11[4];
    const float av[4] = {va.x, va.y, va.z, va.w};
    const float bv[4] = {vb.x, vb.y, vb.z, vb.w};
    const float cv[4] = {vc.x, vc.y, vc.z, vc.w};
    const float dv[4] = {vd.x, vd.y, vd.z, vd.w};

#pragma unroll
    for (int i = 0; i < 4; i++) {
        float t0 = 0.5f * (av[i] + dv[i]);   // .5(a+d)
        float t1 = 0.5f * (av[i] - dv[i]);   // .5(a-d)
        float t2 = 0.5f * (bv[i] + cv[i]);   // .5(b+c)
        float t3 = 0.5f * (bv[i] - cv[i]);   // .5(b-c)
        h00[i] = t0 - t2;   // .5(a-b-c+d)
        h01[i] = t1 + t3;   // .5(a+b-c-d)
        h10[i] = t1 - t3;   // .5(a-b+c-d)
        h11[i] = t0 + t2;   // .5(a+b+c+d)
    }

    int out_row0 = ((b * C_ + ch) * (2 * H_) + (h << 1)) * OW_ + (w4 << 3);
    int out_row1 = out_row0 + OW_;

    stg256(out + out_row0,
           h00[0], h01[0], h00[1], h01[1], h00[2], h01[2], h00[3], h01[3]);
    stg256(out + out_row1,
           h10[0], h11[0], h10[1], h11[1], h10[2], h11[2], h10[3], h11[3]);
}

extern "C" void kernel_launch(void* const* d_in, const int* in_sizes, int n_in,
                              void* d_out, int out_size) {
    const float* x = (const float*)d_in[0];
    float* out = (float*)d_out;

    const int total_threads = B_ * C_ * H_ * WQ_;  // 4,194,304
    const int block = 256;
    const int grid = total_threads / block;        // 16384

    iwt_kernel<<<grid, block>>>(x, out);
}